// round 15
// baseline (speedup 1.0000x reference)
#include <cuda_runtime.h>
#include <cstdint>

#define T_STEPS 2048
#define B_SZ    16
#define D_SZ    1024
#define BD      (B_SZ*D_SZ)          /* 16384 */
#define NCTA    128
#define NTHR    512
#define BG_N    4                    /* batch rows per CTA */
#define CG_N    32                   /* columns per CTA */
#define GROUPS  4                    /* independent sync domains */
#define GSIZE   32                   /* CTAs per domain */

// 128 MB scratch for the precomputed input projection (allowed: __device__ global)
__device__ float    g_xp[(size_t)T_STEPS * BD];
// one monotonic arrival counter per batch-group, padded to separate L2 lines
__device__ unsigned g_cnt[GROUPS * 32];

// ---------------- packed fp32x2 helpers (sm_100+ PTX) ----------------
__device__ __forceinline__ void ffma2(unsigned long long &d,
                                      unsigned long long a,
                                      unsigned long long b) {
    asm("fma.rn.f32x2 %0, %1, %2, %0;" : "+l"(d) : "l"(a), "l"(b));
}
__device__ __forceinline__ float2 unpack2(unsigned long long v) {
    float2 r;
    asm("mov.b64 {%0, %1}, %2;" : "=f"(r.x), "=f"(r.y) : "l"(v));
    return r;
}
__device__ __forceinline__ void cp16(uint32_t dst_smem, const void* src) {
    asm volatile("cp.async.cg.shared.global [%0], [%1], 16;"
                 :: "r"(dst_smem), "l"(src) : "memory");
}
#define CP_COMMIT() asm volatile("cp.async.commit_group;" ::: "memory")
#define CP_WAIT(N)  asm volatile("cp.async.wait_group %0;" :: "n"(N) : "memory")
#define CP_WAIT0()  asm volatile("cp.async.wait_group 0;" ::: "memory")

// ---------------- sync primitives (R7/R13-proven) ----------------
__device__ __forceinline__ unsigned ld_acq(const unsigned* p) {
    unsigned v;
    asm volatile("ld.acquire.gpu.global.u32 %0, [%1];" : "=r"(v) : "l"(p) : "memory");
    return v;
}
__device__ __forceinline__ void red_rel(unsigned* p) {
    asm volatile("red.add.release.gpu.global.u32 [%0], 1;" :: "l"(p) : "memory");
}
__device__ __forceinline__ void bar_sync_id(int id, int cnt) {
    asm volatile("bar.sync %0, %1;" :: "r"(id), "r"(cnt) : "memory");
}

__global__ void init_kernel() {
    if (threadIdx.x < GROUPS * 32) g_cnt[threadIdx.x] = 0u;
}
__global__ void dummy_kernel() { }   // 1 pad: recur lands at ncu launch idx 5

// ---------------------------------------------------------------------
// Kernel 1: xp[m,e] = sum_d x[m,d]*Wx[e,d] + b[e]
// REWRITTEN: 64x64 tile, BK=32, cp.async double-buffered, k-vectorized
// 4x4 micro-tile (packed f32x2 accumulators, horizontal add at end),
// XOR-swizzled smem (chunk ^ (row&7)) for conflict-free LDS.128.
// ---------------------------------------------------------------------
__global__ __launch_bounds__(256) void xp_gemm_kernel(
    const float* __restrict__ X,
    const float* __restrict__ Wx,
    const float* __restrict__ bias)
{
    // [buf][row 0..63][8 chunks of float4], swizzled chunk position
    __shared__ __align__(16) float As[2][64 * 32];
    __shared__ __align__(16) float Bs[2][64 * 32];

    const int tid   = threadIdx.x;
    const int mBase = blockIdx.y * 64;
    const int nBase = blockIdx.x * 64;

    const int ty = tid >> 4;           // 0..15 -> m group of 4
    const int tx = tid & 15;           // 0..15 -> n group of 4
    const int m0 = ty * 4, n0 = tx * 4;

    const uint32_t a_sh = (uint32_t)__cvta_generic_to_shared(&As[0][0]);
    const uint32_t b_sh = (uint32_t)__cvta_generic_to_shared(&Bs[0][0]);

    // staging: 512 f4 pieces per tile; 2 cp16/thread per tile
    // piece p: row = p>>3, chunk c = p&7, dst chunk' = c ^ (row&7)
    auto stage = [&](int buf, int k0) {
#pragma unroll
        for (int j = 0; j < 2; j++) {
            const int p   = tid + 256 * j;
            const int row = p >> 3;
            const int c   = p & 7;
            const int q   = row * 8 + (c ^ (row & 7));      // swizzled f4 idx
            cp16(a_sh + (uint32_t)(buf * 2048 + q * 4) * 4u,
                 X + (size_t)(mBase + row) * 1024 + k0 + c * 4);
            cp16(b_sh + (uint32_t)(buf * 2048 + q * 4) * 4u,
                 Wx + (size_t)(nBase + row) * 1024 + k0 + c * 4);
        }
        CP_COMMIT();
    };

    stage(0, 0);

    unsigned long long acc[4][4];
#pragma unroll
    for (int j = 0; j < 4; j++)
#pragma unroll
        for (int i = 0; i < 4; i++) acc[j][i] = 0ull;

    for (int ch = 0; ch < 32; ch++) {
        if (ch < 31) { stage((ch + 1) & 1, (ch + 1) * 32); CP_WAIT(1); }
        else         { CP_WAIT0(); }
        __syncthreads();                       // chunk ch fully staged

        const float* Ab = &As[ch & 1][0];
        const float* Bb = &Bs[ch & 1][0];
#pragma unroll
        for (int c = 0; c < 8; c++) {
            ulonglong2 b4[4];
#pragma unroll
            for (int i = 0; i < 4; i++) {
                const int row = n0 + i;
                b4[i] = *reinterpret_cast<const ulonglong2*>(
                    Bb + (row * 8 + (c ^ (row & 7))) * 4);
            }
#pragma unroll
            for (int j = 0; j < 4; j++) {
                const int row = m0 + j;
                ulonglong2 a4 = *reinterpret_cast<const ulonglong2*>(
                    Ab + (row * 8 + (c ^ (row & 7))) * 4);
#pragma unroll
                for (int i = 0; i < 4; i++) {
                    ffma2(acc[j][i], a4.x, b4[i].x);
                    ffma2(acc[j][i], a4.y, b4[i].y);
                }
            }
        }
        __syncthreads();                       // done reading buf before reuse
    }

    const int col = nBase + n0;
    const float4 bv = *reinterpret_cast<const float4*>(&bias[col]);
#pragma unroll
    for (int j = 0; j < 4; j++) {
        const int row = mBase + m0 + j;
        float2 p0 = unpack2(acc[j][0]);
        float2 p1 = unpack2(acc[j][1]);
        float2 p2 = unpack2(acc[j][2]);
        float2 p3 = unpack2(acc[j][3]);
        float4 r;
        r.x = (p0.x + p0.y) + bv.x;
        r.y = (p1.x + p1.y) + bv.y;
        r.z = (p2.x + p2.y) + bv.z;
        r.w = (p3.x + p3.y) + bv.w;
        *reinterpret_cast<float4*>(&g_xp[(size_t)row * 1024 + col]) = r;
    }
}

// ---------------------------------------------------------------------
// Kernel 2: persistent recurrence — EXACTLY R13 (proven 7.20 ms).
// 128 CTAs x 512 threads = 4 independent groups (bg = cta&3, 4 b-rows)
// x 32 col-slices (ng = cta>>2, 32 cols). Per step: tid0 poll + B1;
// each warp stages ONLY its 1KB h chunk (warp-local wait); 256 MACs/
// thread with register-resident W_h; partials; B3; epilogue warps
// reduce+store h, converge on bar.sync(1,128), tid0 early-releases.
// ---------------------------------------------------------------------
__global__ __launch_bounds__(512, 1) void recur_kernel(
    const float* __restrict__ Z,
    const float* __restrict__ H0,
    const float* __restrict__ Wh,
    const float* __restrict__ Gz,
    const float* __restrict__ Gh,
    const float* __restrict__ Bg,
    float* __restrict__ Out,
    float* __restrict__ Hout)
{
    extern __shared__ __align__(16) float sm[];
    float* h_s = sm;                       // [16 warps][4 rows][64] = 4096 f
    float* red = sm + 4096;                // [16][32][4] = 2048 f

    const int tid  = threadIdx.x;
    const int ks   = tid >> 5;             // k-sixteenth 0..15 (= warp)
    const int n    = tid & 31;             // column within CTA 0..31
    const int cta  = blockIdx.x;

    const int bg    = cta & 3;             // batch group (independent domain)
    const int ng    = cta >> 2;            // column slice 0..31
    const int bbase = bg * BG_N;
    const int gcol  = ng * CG_N + n;

    unsigned* cnt = &g_cnt[bg * 32];

    // ---- W_h slice (64 floats) -> registers, resident for all steps ----
    unsigned long long wx[16], wy[16];
    {
        const float* wp = Wh + (size_t)gcol * 1024 + ks * 64;
#pragma unroll
        for (int i = 0; i < 16; i++) {
            ulonglong2 v = *reinterpret_cast<const ulonglong2*>(wp + i * 4);
            wx[i] = v.x; wy[i] = v.y;
        }
    }

    // ---- warp-local staging pieces (2 x 16B per lane, own k-chunk) ----
    const uint32_t h_sh = (uint32_t)__cvta_generic_to_shared(h_s);
    const int r0 = n >> 4,        c0 = n & 15;
    const int r1 = (n + 32) >> 4, c1 = (n + 32) & 15;
    const uint32_t dst0 = h_sh + (uint32_t)(ks * 256 + r0 * 64 + c0 * 4) * 4u;
    const uint32_t dst1 = h_sh + (uint32_t)(ks * 256 + r1 * 64 + c1 * 4) * 4u;
    const int soff0 = (bbase + r0) * 1024 + ks * 64 + c0 * 4;
    const int soff1 = (bbase + r1) * 1024 + ks * 64 + c1 * 4;

    // ---- epilogue role (threads 0..127): eb = tid&3, en = tid>>2 ----
    const int eb  = tid & 3;
    const int en  = tid >> 2;
    const int egb = bbase + eb;
    const int egc = ng * CG_N + en;
    float gz_r = 0.f, gh_r = 0.f, bg_r = 0.f;
    if (tid < 128) {
        gz_r = Gz[egc]; gh_r = Gh[egc]; bg_r = Bg[egc];
        // h[0] = h0 (required output row 0; also the t=0 staging source)
        __stcg(&Hout[(size_t)egb * 1024 + egc], H0[(size_t)egb * 1024 + egc]);
    }
    __syncthreads();
    if (tid == 0) red_rel(cnt);            // publish h[0] slice

    for (int t = 0; t < T_STEPS; ++t) {
        // ---- prefetch epilogue operands (independent of h) ----
        float xpv = 0.f, zv = 0.f;
        size_t eidx = 0;
        if (tid < 128) {
            eidx = (size_t)t * BD + (size_t)egb * 1024 + egc;
            xpv = __ldcg(&g_xp[eidx]);
            zv  = __ldcg(&Z[eidx]);
        }

        // ---- group barrier: wait for all 32 peers to publish h[t] ----
        if (tid == 0) {
            const unsigned target = (unsigned)GSIZE * (unsigned)(t + 1);
            while (ld_acq(cnt) < target) { }
        }
        __syncthreads();                           // B1

        // ---- warp-local staging of this warp's 1KB h chunk ----
        const float* hbase = Hout + (size_t)t * BD;
        cp16(dst0, hbase + soff0);
        cp16(dst1, hbase + soff1);
        CP_COMMIT();
        CP_WAIT0();
        __syncwarp();

        // ---- dot products: 256 MACs/thread (64k x 4b), h broadcast ----
        unsigned long long accA[4] = {0ull, 0ull, 0ull, 0ull};
        unsigned long long accB[4] = {0ull, 0ull, 0ull, 0ull};
        const float* hc = h_s + ks * 256;
#pragma unroll
        for (int i = 0; i < 16; i++) {
#pragma unroll
            for (int b = 0; b < 4; b++) {
                ulonglong2 hv = *reinterpret_cast<const ulonglong2*>(
                    hc + b * 64 + i * 4);
                ffma2(accA[b], hv.x, wx[i]);
                ffma2(accB[b], hv.y, wy[i]);
            }
        }

        // ---- partials -> red[ks][n][b] (conflict-free f4 store) ----
        float s4[4];
#pragma unroll
        for (int b = 0; b < 4; b++) {
            float2 a = unpack2(accA[b]);
            float2 c = unpack2(accB[b]);
            s4[b] = (a.x + a.y) + (c.x + c.y);
        }
        *reinterpret_cast<float4*>(red + (ks * 32 + n) * 4) =
            make_float4(s4[0], s4[1], s4[2], s4[3]);
        __syncthreads();                           // B3

        // ---- epilogue warps only: reduce, activation, publish ----
        if (tid < 128) {
            float dot = 0.f;
#pragma unroll
            for (int k = 0; k < 16; k++)
                dot += red[k * 128 + tid];          // coalesced
            const float hn = tanhf(xpv + dot);
            __stcg(&Hout[(size_t)(t + 1) * BD + (size_t)egb * 1024 + egc], hn);

            bar_sync_id(1, 128);                   // epi-only convergence
            if (tid == 0) red_rel(cnt);            // early release

            // gate + Out store: off the critical path
            const float pre = zv * gz_r + hn * gh_r + bg_r;
            const float sg  = 1.0f / (1.0f + __expf(-pre));
            __stcg(&Out[eidx], hn * (pre * sg));
        }
        // compute warps loop directly to the next B1 (red WAR is guarded
        // by B1: it admits nobody until epi warps arrive there too)
    }
}

// ---------------------------------------------------------------------
extern "C" void kernel_launch(void* const* d_in, const int* in_sizes, int n_in,
                              void* d_out, int out_size)
{
    const float* x  = (const float*)d_in[0];
    const float* z  = (const float*)d_in[1];
    const float* h0 = (const float*)d_in[2];
    const float* Wx = (const float*)d_in[3];
    const float* Wh = (const float*)d_in[4];
    const float* b  = (const float*)d_in[5];
    const float* gz = (const float*)d_in[6];
    const float* gh = (const float*)d_in[7];
    const float* bg = (const float*)d_in[8];

    float* out  = (float*)d_out;                       // [T,B,D]
    float* hout = out + (size_t)T_STEPS * BD;          // [T+1,B,D]

    init_kernel<<<1, 128>>>();                         // my launch 0

    dim3 gGemm(1024 / 64, (T_STEPS * B_SZ) / 64);      // (16, 512)
    xp_gemm_kernel<<<gGemm, 256>>>(x, Wx, b);          // my launch 1

    dummy_kernel<<<1, 1>>>();                          // my launch 2
                                                       // (+2 harness -> recur idx 5)

    // actual need 24KB; pad to force 1 CTA/SM (all 128 CTAs resident,
    // required for the group counters to make progress).
    const int smem_bytes = 118784;
    cudaFuncSetAttribute(recur_kernel,
                         cudaFuncAttributeMaxDynamicSharedMemorySize, smem_bytes);
    recur_kernel<<<NCTA, NTHR, smem_bytes>>>(z, h0, Wh, gz, gh, bg, out, hout);
}

// round 17
// speedup vs baseline: 1.3378x; 1.3378x over previous
#include <cuda_runtime.h>
#include <cstdint>

#define T_STEPS 2048
#define B_SZ    16
#define D_SZ    1024
#define BD      (B_SZ*D_SZ)          /* 16384 */
#define NCTA    128
#define NTHR    512
#define BG_N    4                    /* batch rows per CTA */
#define CG_N    32                   /* columns per CTA */
#define GROUPS  4                    /* independent sync domains */
#define GSIZE   32                   /* CTAs per domain */

// 128 MB scratch for the precomputed input projection (allowed: __device__ global)
__device__ float    g_xp[(size_t)T_STEPS * BD];
// one monotonic arrival counter per batch-group, padded to separate L2 lines
__device__ unsigned g_cnt[GROUPS * 32];

// ---------------- packed fp32x2 helpers (sm_100+ PTX) ----------------
__device__ __forceinline__ void ffma2(unsigned long long &d,
                                      unsigned long long a,
                                      unsigned long long b) {
    asm("fma.rn.f32x2 %0, %1, %2, %0;" : "+l"(d) : "l"(a), "l"(b));
}
__device__ __forceinline__ float2 unpack2(unsigned long long v) {
    float2 r;
    asm("mov.b64 {%0, %1}, %2;" : "=f"(r.x), "=f"(r.y) : "l"(v));
    return r;
}
__device__ __forceinline__ void cp16(uint32_t dst_smem, const void* src) {
    asm volatile("cp.async.cg.shared.global [%0], [%1], 16;"
                 :: "r"(dst_smem), "l"(src) : "memory");
}
#define CP_COMMIT() asm volatile("cp.async.commit_group;" ::: "memory")
#define CP_WAIT(N)  asm volatile("cp.async.wait_group %0;" :: "n"(N) : "memory")
#define CP_WAIT0()  asm volatile("cp.async.wait_group 0;" ::: "memory")

// ---------------- sync primitives (R7/R13-proven) ----------------
__device__ __forceinline__ unsigned ld_acq(const unsigned* p) {
    unsigned v;
    asm volatile("ld.acquire.gpu.global.u32 %0, [%1];" : "=r"(v) : "l"(p) : "memory");
    return v;
}
__device__ __forceinline__ void red_rel(unsigned* p) {
    asm volatile("red.add.release.gpu.global.u32 [%0], 1;" :: "l"(p) : "memory");
}
__device__ __forceinline__ void bar_sync_id(int id, int cnt) {
    asm volatile("bar.sync %0, %1;" :: "r"(id), "r"(cnt) : "memory");
}

__global__ void init_kernel() {
    if (threadIdx.x < GROUPS * 32) g_cnt[threadIdx.x] = 0u;
}
__global__ void dummy_kernel() { }   // 1 pad: recur lands at ncu launch idx 5

// ---------------------------------------------------------------------
// Kernel 1: xp[m,e] = sum_d x[m,d]*Wx[e,d] + b[e]
// 64x64 tile, BK=32, cp.async double-buffered, 4x4 micro-tile with
// packed f32x2 accumulators. SWIZZLE FIX vs R14: chunk' = c ^ ((row>>2)&7)
// — B-loads read rows 4*tx+i, so (row>>2)&7 = tx&7 spreads the 16 lanes
// over all 8 swizzled columns (R14's row&7 collapsed them onto 2 ->
// 8-way conflicts). Staging uses the same formula (layout-invariant).
// ---------------------------------------------------------------------
__global__ __launch_bounds__(256) void xp_gemm_kernel(
    const float* __restrict__ X,
    const float* __restrict__ Wx,
    const float* __restrict__ bias)
{
    // [buf][row 0..63][8 chunks of float4], swizzled chunk position
    __shared__ __align__(16) float As[2][64 * 32];
    __shared__ __align__(16) float Bs[2][64 * 32];

    const int tid   = threadIdx.x;
    const int mBase = blockIdx.y * 64;
    const int nBase = blockIdx.x * 64;

    const int ty = tid >> 4;           // 0..15 -> m group of 4
    const int tx = tid & 15;           // 0..15 -> n group of 4
    const int m0 = ty * 4, n0 = tx * 4;

    const uint32_t a_sh = (uint32_t)__cvta_generic_to_shared(&As[0][0]);
    const uint32_t b_sh = (uint32_t)__cvta_generic_to_shared(&Bs[0][0]);

    // staging: 512 f4 pieces per tile; 2 cp16/thread per tile
    // piece p: row = p>>3, chunk c = p&7, dst chunk' = c ^ ((row>>2)&7)
    auto stage = [&](int buf, int k0) {
#pragma unroll
        for (int j = 0; j < 2; j++) {
            const int p   = tid + 256 * j;
            const int row = p >> 3;
            const int c   = p & 7;
            const int q   = row * 8 + (c ^ ((row >> 2) & 7));  // swizzled f4
            cp16(a_sh + (uint32_t)(buf * 2048 + q * 4) * 4u,
                 X + (size_t)(mBase + row) * 1024 + k0 + c * 4);
            cp16(b_sh + (uint32_t)(buf * 2048 + q * 4) * 4u,
                 Wx + (size_t)(nBase + row) * 1024 + k0 + c * 4);
        }
        CP_COMMIT();
    };

    stage(0, 0);

    unsigned long long acc[4][4];
#pragma unroll
    for (int j = 0; j < 4; j++)
#pragma unroll
        for (int i = 0; i < 4; i++) acc[j][i] = 0ull;

    for (int ch = 0; ch < 32; ch++) {
        if (ch < 31) { stage((ch + 1) & 1, (ch + 1) * 32); CP_WAIT(1); }
        else         { CP_WAIT0(); }
        __syncthreads();                       // chunk ch fully staged

        const float* Ab = &As[ch & 1][0];
        const float* Bb = &Bs[ch & 1][0];
#pragma unroll
        for (int c = 0; c < 8; c++) {
            ulonglong2 b4[4];
#pragma unroll
            for (int i = 0; i < 4; i++) {
                const int row = n0 + i;
                b4[i] = *reinterpret_cast<const ulonglong2*>(
                    Bb + (row * 8 + (c ^ ((row >> 2) & 7))) * 4);
            }
#pragma unroll
            for (int j = 0; j < 4; j++) {
                const int row = m0 + j;
                ulonglong2 a4 = *reinterpret_cast<const ulonglong2*>(
                    Ab + (row * 8 + (c ^ ((row >> 2) & 7))) * 4);
#pragma unroll
                for (int i = 0; i < 4; i++) {
                    ffma2(acc[j][i], a4.x, b4[i].x);
                    ffma2(acc[j][i], a4.y, b4[i].y);
                }
            }
        }
        __syncthreads();                       // done reading buf before reuse
    }

    const int col = nBase + n0;
    const float4 bv = *reinterpret_cast<const float4*>(&bias[col]);
#pragma unroll
    for (int j = 0; j < 4; j++) {
        const int row = mBase + m0 + j;
        float2 p0 = unpack2(acc[j][0]);
        float2 p1 = unpack2(acc[j][1]);
        float2 p2 = unpack2(acc[j][2]);
        float2 p3 = unpack2(acc[j][3]);
        float4 r;
        r.x = (p0.x + p0.y) + bv.x;
        r.y = (p1.x + p1.y) + bv.y;
        r.z = (p2.x + p2.y) + bv.z;
        r.w = (p3.x + p3.y) + bv.w;
        *reinterpret_cast<float4*>(&g_xp[(size_t)row * 1024 + col]) = r;
    }
}

// ---------------------------------------------------------------------
// Kernel 2: persistent recurrence — EXACTLY R13 (proven 7.20 ms).
// 128 CTAs x 512 threads = 4 independent groups (bg = cta&3, 4 b-rows)
// x 32 col-slices (ng = cta>>2, 32 cols). Per step: tid0 poll + B1;
// each warp stages ONLY its 1KB h chunk (warp-local wait); 256 MACs/
// thread with register-resident W_h; partials; B3; epilogue warps
// reduce+store h, converge on bar.sync(1,128), tid0 early-releases.
// ---------------------------------------------------------------------
__global__ __launch_bounds__(512, 1) void recur_kernel(
    const float* __restrict__ Z,
    const float* __restrict__ H0,
    const float* __restrict__ Wh,
    const float* __restrict__ Gz,
    const float* __restrict__ Gh,
    const float* __restrict__ Bg,
    float* __restrict__ Out,
    float* __restrict__ Hout)
{
    extern __shared__ __align__(16) float sm[];
    float* h_s = sm;                       // [16 warps][4 rows][64] = 4096 f
    float* red = sm + 4096;                // [16][32][4] = 2048 f

    const int tid  = threadIdx.x;
    const int ks   = tid >> 5;             // k-sixteenth 0..15 (= warp)
    const int n    = tid & 31;             // column within CTA 0..31
    const int cta  = blockIdx.x;

    const int bg    = cta & 3;             // batch group (independent domain)
    const int ng    = cta >> 2;            // column slice 0..31
    const int bbase = bg * BG_N;
    const int gcol  = ng * CG_N + n;

    unsigned* cnt = &g_cnt[bg * 32];

    // ---- W_h slice (64 floats) -> registers, resident for all steps ----
    unsigned long long wx[16], wy[16];
    {
        const float* wp = Wh + (size_t)gcol * 1024 + ks * 64;
#pragma unroll
        for (int i = 0; i < 16; i++) {
            ulonglong2 v = *reinterpret_cast<const ulonglong2*>(wp + i * 4);
            wx[i] = v.x; wy[i] = v.y;
        }
    }

    // ---- warp-local staging pieces (2 x 16B per lane, own k-chunk) ----
    const uint32_t h_sh = (uint32_t)__cvta_generic_to_shared(h_s);
    const int r0 = n >> 4,        c0 = n & 15;
    const int r1 = (n + 32) >> 4, c1 = (n + 32) & 15;
    const uint32_t dst0 = h_sh + (uint32_t)(ks * 256 + r0 * 64 + c0 * 4) * 4u;
    const uint32_t dst1 = h_sh + (uint32_t)(ks * 256 + r1 * 64 + c1 * 4) * 4u;
    const int soff0 = (bbase + r0) * 1024 + ks * 64 + c0 * 4;
    const int soff1 = (bbase + r1) * 1024 + ks * 64 + c1 * 4;

    // ---- epilogue role (threads 0..127): eb = tid&3, en = tid>>2 ----
    const int eb  = tid & 3;
    const int en  = tid >> 2;
    const int egb = bbase + eb;
    const int egc = ng * CG_N + en;
    float gz_r = 0.f, gh_r = 0.f, bg_r = 0.f;
    if (tid < 128) {
        gz_r = Gz[egc]; gh_r = Gh[egc]; bg_r = Bg[egc];
        // h[0] = h0 (required output row 0; also the t=0 staging source)
        __stcg(&Hout[(size_t)egb * 1024 + egc], H0[(size_t)egb * 1024 + egc]);
    }
    __syncthreads();
    if (tid == 0) red_rel(cnt);            // publish h[0] slice

    for (int t = 0; t < T_STEPS; ++t) {
        // ---- prefetch epilogue operands (independent of h) ----
        float xpv = 0.f, zv = 0.f;
        size_t eidx = 0;
        if (tid < 128) {
            eidx = (size_t)t * BD + (size_t)egb * 1024 + egc;
            xpv = __ldcg(&g_xp[eidx]);
            zv  = __ldcg(&Z[eidx]);
        }

        // ---- group barrier: wait for all 32 peers to publish h[t] ----
        if (tid == 0) {
            const unsigned target = (unsigned)GSIZE * (unsigned)(t + 1);
            while (ld_acq(cnt) < target) { }
        }
        __syncthreads();                           // B1

        // ---- warp-local staging of this warp's 1KB h chunk ----
        const float* hbase = Hout + (size_t)t * BD;
        cp16(dst0, hbase + soff0);
        cp16(dst1, hbase + soff1);
        CP_COMMIT();
        CP_WAIT0();
        __syncwarp();

        // ---- dot products: 256 MACs/thread (64k x 4b), h broadcast ----
        unsigned long long accA[4] = {0ull, 0ull, 0ull, 0ull};
        unsigned long long accB[4] = {0ull, 0ull, 0ull, 0ull};
        const float* hc = h_s + ks * 256;
#pragma unroll
        for (int i = 0; i < 16; i++) {
#pragma unroll
            for (int b = 0; b < 4; b++) {
                ulonglong2 hv = *reinterpret_cast<const ulonglong2*>(
                    hc + b * 64 + i * 4);
                ffma2(accA[b], hv.x, wx[i]);
                ffma2(accB[b], hv.y, wy[i]);
            }
        }

        // ---- partials -> red[ks][n][b] (conflict-free f4 store) ----
        float s4[4];
#pragma unroll
        for (int b = 0; b < 4; b++) {
            float2 a = unpack2(accA[b]);
            float2 c = unpack2(accB[b]);
            s4[b] = (a.x + a.y) + (c.x + c.y);
        }
        *reinterpret_cast<float4*>(red + (ks * 32 + n) * 4) =
            make_float4(s4[0], s4[1], s4[2], s4[3]);
        __syncthreads();                           // B3

        // ---- epilogue warps only: reduce, activation, publish ----
        if (tid < 128) {
            float dot = 0.f;
#pragma unroll
            for (int k = 0; k < 16; k++)
                dot += red[k * 128 + tid];          // coalesced
            const float hn = tanhf(xpv + dot);
            __stcg(&Hout[(size_t)(t + 1) * BD + (size_t)egb * 1024 + egc], hn);

            bar_sync_id(1, 128);                   // epi-only convergence
            if (tid == 0) red_rel(cnt);            // early release

            // gate + Out store: off the critical path
            const float pre = zv * gz_r + hn * gh_r + bg_r;
            const float sg  = 1.0f / (1.0f + __expf(-pre));
            __stcg(&Out[eidx], hn * (pre * sg));
        }
        // compute warps loop directly to the next B1 (red WAR is guarded
        // by B1: it admits nobody until epi warps arrive there too)
    }
}

// ---------------------------------------------------------------------
extern "C" void kernel_launch(void* const* d_in, const int* in_sizes, int n_in,
                              void* d_out, int out_size)
{
    const float* x  = (const float*)d_in[0];
    const float* z  = (const float*)d_in[1];
    const float* h0 = (const float*)d_in[2];
    const float* Wx = (const float*)d_in[3];
    const float* Wh = (const float*)d_in[4];
    const float* b  = (const float*)d_in[5];
    const float* gz = (const float*)d_in[6];
    const float* gh = (const float*)d_in[7];
    const float* bg = (const float*)d_in[8];

    float* out  = (float*)d_out;                       // [T,B,D]
    float* hout = out + (size_t)T_STEPS * BD;          // [T+1,B,D]

    init_kernel<<<1, 128>>>();                         // my launch 0

    dim3 gGemm(1024 / 64, (T_STEPS * B_SZ) / 64);      // (16, 512)
    xp_gemm_kernel<<<gGemm, 256>>>(x, Wx, b);          // my launch 1

    dummy_kernel<<<1, 1>>>();                          // my launch 2
                                                       // (+2 harness -> recur idx 5)

    // actual need 24KB; pad to force 1 CTA/SM (all 128 CTAs resident,
    // required for the group counters to make progress).
    const int smem_bytes = 118784;
    cudaFuncSetAttribute(recur_kernel,
                         cudaFuncAttributeMaxDynamicSharedMemorySize, smem_bytes);
    recur_kernel<<<NCTA, NTHR, smem_bytes>>>(z, h0, Wh, gz, gh, bg, out, hout);
}